// round 14
// baseline (speedup 1.0000x reference)
#include <cuda_runtime.h>

// ---------------------------------------------------------------------------
// SLAYER SRM-alpha SNN forward, t-major layout [t*N + n].
// R13: convs split spatially into 256 blocks x 128 thr (all 148 SMs covered,
// 2 co-resident blocks/SM overlap each other's stalls). Conflict-free padded
// smem strides (conv1 CS=144, conv2 CS=26). Arithmetic bit-exact vs R12.
// ---------------------------------------------------------------------------

#define T_STEPS 300

__device__ float g_s0[16384 * T_STEPS];   // pool0 potentials -> spikes (B,2,32,32)
__device__ float g_s2[32768 * T_STEPS];   // pool1 spikes (B,16,16,16)
__device__ float g_s4[16384 * T_STEPS];   // pool2 spikes (B,32,8,8)
__device__ float g_u5[4096  * T_STEPS];   // fc1 potentials -> spikes in place
__device__ float g_u6[88    * T_STEPS];   // fc2 potentials

typedef unsigned long long u64_t;

// ---- fp32x2 packed helpers --------------------------------------------------
__device__ __forceinline__ u64_t pk2(float lo, float hi) {
    u64_t r; asm("mov.b64 %0,{%1,%2};" : "=l"(r) : "f"(lo), "f"(hi)); return r;
}
__device__ __forceinline__ u64_t dup2(float x) {
    u64_t r; asm("mov.b64 %0,{%1,%1};" : "=l"(r) : "f"(x)); return r;
}
__device__ __forceinline__ void upk2(u64_t v, float& lo, float& hi) {
    asm("mov.b64 {%0,%1},%2;" : "=f"(lo), "=f"(hi) : "l"(v));
}
__device__ __forceinline__ u64_t fma2(u64_t a, u64_t b, u64_t c) {
    u64_t d; asm("fma.rn.f32x2 %0,%1,%2,%3;" : "=l"(d) : "l"(a), "l"(b), "l"(c)); return d;
}
__device__ __forceinline__ u64_t mul2(u64_t a, u64_t b) {
    u64_t d; asm("mul.rn.f32x2 %0,%1,%2;" : "=l"(d) : "l"(a), "l"(b)); return d;
}
__device__ __forceinline__ u64_t add2(u64_t a, u64_t b) {
    u64_t d; asm("add.rn.f32x2 %0,%1,%2;" : "=l"(d) : "l"(a), "l"(b)); return d;
}

// ---- SRM constants ----------------------------------------------------------
#define SRM_D  0.36787944117144233f   // exp(-1)
#define SRM_CE 2.7182818284590452f    // e
#define SRM_CR -54.365636569180905f   // -2*theta*e

struct Srm { float p1, q1, p2, q2; };

__device__ __forceinline__ float srm_step(Srm& s, float u) {
    s.q1 = __fmul_rn(SRM_D, __fadd_rn(s.q1, s.p1));
    s.p1 = __fadd_rn(__fmul_rn(SRM_D, s.p1), u);
    float y = __fmul_rn(SRM_CE, s.q1);
    s.q2 = __fmul_rn(SRM_D, __fadd_rn(s.q2, s.p2));
    float sp = (__fadd_rn(y, __fmul_rn(SRM_CR, s.q2)) >= 10.0f) ? 1.0f : 0.0f;
    s.p2 = __fadd_rn(__fmul_rn(SRM_D, s.p2), sp);
    return sp;
}

struct Srm2 { u64_t p1, q1, p2, q2; };

__device__ __forceinline__ void srm2_step(Srm2& s, u64_t u, float& slo, float& shi) {
    const u64_t D2  = dup2(SRM_D);
    const u64_t CE2 = dup2(SRM_CE);
    const u64_t CR2 = dup2(SRM_CR);
    s.q1 = mul2(D2, add2(s.q1, s.p1));
    s.p1 = add2(mul2(D2, s.p1), u);
    u64_t y = mul2(CE2, s.q1);
    s.q2 = mul2(D2, add2(s.q2, s.p2));
    u64_t m = add2(y, mul2(CR2, s.q2));
    float mlo, mhi; upk2(m, mlo, mhi);
    slo = (mlo >= 10.0f) ? 1.0f : 0.0f;
    shi = (mhi >= 10.0f) ? 1.0f : 0.0f;
    s.p2 = add2(mul2(D2, s.p2), pk2(slo, shi));
}

__device__ __forceinline__ u64_t srm2_step_pk(Srm2& s, u64_t u) {
    float slo, shi;
    srm2_step(s, u, slo, shi);
    return pk2(slo, shi);
}

__device__ __forceinline__ void cp_async4(void* sm, const void* gm) {
    unsigned s = (unsigned)__cvta_generic_to_shared(sm);
    asm volatile("cp.async.ca.shared.global [%0], [%1], 4;" :: "r"(s), "l"(gm));
}
__device__ __forceinline__ void cp_commit() { asm volatile("cp.async.commit_group;"); }
__device__ __forceinline__ void cp_wait0()  { asm volatile("cp.async.wait_group 0;" ::: "memory"); }

// ---------------------------------------------------------------------------
// K0: 4x4 sum-pool (gain 11) + transpose (B,2,128,128,T) -> t-major g_s0.
// ---------------------------------------------------------------------------
__global__ void pool0_transpose_kernel(const float* __restrict__ x) {
    __shared__ float sm[128][33];
    const int tx = threadIdx.x, ty = threadIdx.y;
    const int tb = blockIdx.x;
    const int nb = blockIdx.y;
    const int ho = nb & 31, bc = nb >> 5;
    const int tq = tb * 32 + tx;
    if (tq < 75) {
        const float* base = x + (size_t)((bc * 128 + ho * 4) * 128) * 300 + tq * 4;
        for (int j = ty; j < 32; j += 8) {
            float ax = 0.f, ay = 0.f, az = 0.f, aw = 0.f;
            #pragma unroll
            for (int dy = 0; dy < 4; ++dy) {
                const float* rp = base + (size_t)(dy * 128 + j * 4) * 300;
                float4 v0 = *(const float4*)(rp);
                float4 v1 = *(const float4*)(rp + 300);
                float4 v2 = *(const float4*)(rp + 600);
                float4 v3 = *(const float4*)(rp + 900);
                ax += ((v0.x + v1.x) + v2.x) + v3.x;
                ay += ((v0.y + v1.y) + v2.y) + v3.y;
                az += ((v0.z + v1.z) + v2.z) + v3.z;
                aw += ((v0.w + v1.w) + v2.w) + v3.w;
            }
            sm[tx * 4 + 0][j] = 11.0f * ax;
            sm[tx * 4 + 1][j] = 11.0f * ay;
            sm[tx * 4 + 2][j] = 11.0f * az;
            sm[tx * 4 + 3][j] = 11.0f * aw;
        }
    }
    __syncthreads();
    for (int tt = ty; tt < 128; tt += 8) {
        int t2 = tb * 128 + tt;
        if (t2 < T_STEPS)
            g_s0[t2 * 16384 + nb * 32 + tx] = sm[tt][tx];
    }
}

// ---- packed in-place psp+spike scan (2 neurons/thread, manual prefetch) ----
__device__ __forceinline__ void scan_body2(float* buf, int N) {
    int n2 = blockIdx.x * blockDim.x + threadIdx.x;
    if (n2 >= N / 2) return;
    Srm2 st = {0, 0, 0, 0};
    float* p = buf + 2 * n2;
    float2 v = *(float2*)p;
    #pragma unroll 1
    for (int t = 0; t < T_STEPS; ++t) {
        float2 vn = v;
        if (t + 1 < T_STEPS) vn = *(float2*)(p + (t + 1) * N);
        float slo, shi;
        srm2_step(st, pk2(v.x, v.y), slo, shi);
        *(float2*)(p + t * N) = make_float2(slo, shi);
        v = vn;
    }
}
__global__ void scan_s0_kernel() { scan_body2(g_s0, 16384); }
__global__ void scan_u5_kernel() { scan_body2(g_u5, 4096); }

// ---------------------------------------------------------------------------
// conv1 (5x5,pad2,2->16) + psp+spike + 2x2 pool + psp+spike, fused.
// R13 split: grid (hp=16, b=8, xq=2), 128 thr: xp = tid[0:2], kh = tid[3],
// co = tid>>4 (0..7; channels co & co+8 f32x2-packed). Tile: 2ci x 6r x 20c,
// channel stride padded to 144 (kh1 -> bank 16: conflict-free).
// Reduce-scatter over kh (mask 8) + per-lane srm ownership.
// ---------------------------------------------------------------------------
#define C1_CS 144
__global__ void __launch_bounds__(128) conv1_fused_kernel(const float* __restrict__ W1) {
    __shared__ float sbuf[2][2 * C1_CS];   // [buf][ci*144 + r*20 + c]
    const int tid = threadIdx.x;
    const int xp  = tid & 7;
    const int kh  = (tid >> 3) & 1;
    const int co  = tid >> 4;             // 0..7 -> channels co, co+8
    const int hp  = blockIdx.x;           // 0..15
    const int b   = blockIdx.y;
    const int xq  = blockIdx.z;           // 0..1
    u64_t wp[25];
    #pragma unroll
    for (int k = 0; k < 25; ++k)
        wp[k] = pk2(W1[co * 50 + kh * 25 + k], W1[(co + 8) * 50 + kh * 25 + k]);
    for (int i = tid; i < 2 * 2 * C1_CS; i += 128) ((float*)sbuf)[i] = 0.f;

    // staging: slots tid, tid+128, tid+256 (288 total)
    bool sv[3] = {false, false, false}; int gg[3] = {0, 0, 0};
    #pragma unroll
    for (int e = 0; e < 3; ++e) {
        int i = tid + e * 128;
        if (i >= 2 * C1_CS) break;
        int ci = i / C1_CS, rem = i - ci * C1_CS;
        if (rem < 120) {
            int r = rem / 20, c = rem - r * 20;
            int row = 2 * hp + r - 2, col = xq * 16 + c - 2;
            if (row >= 0 && row < 32 && col >= 0 && col < 32) {
                sv[e] = true; gg[e] = b * 2048 + ci * 1024 + row * 32 + col;
            }
        }
    }
    __syncthreads();

    if (sv[0]) cp_async4(&sbuf[0][tid],       g_s0 + gg[0]);
    if (sv[1]) cp_async4(&sbuf[0][tid + 128], g_s0 + gg[1]);
    if (sv[2]) cp_async4(&sbuf[0][tid + 256], g_s0 + gg[2]);
    cp_commit(); cp_wait0();
    __syncthreads();

    Srm2 st0 = {0,0,0,0}, st1 = {0,0,0,0}, stP = {0,0,0,0};
    const int outIdx = ((b * 16 + co) * 16 + hp) * 16 + xq * 8 + xp;  // ch1 +2048

    #pragma unroll 1
    for (int t = 0; t < T_STEPS; ++t) {
        const int cur = t & 1;
        if (t + 1 < T_STEPS) {
            const float* fr = g_s0 + (t + 1) * 16384;
            if (sv[0]) cp_async4(&sbuf[cur ^ 1][tid],       fr + gg[0]);
            if (sv[1]) cp_async4(&sbuf[cur ^ 1][tid + 128], fr + gg[1]);
            if (sv[2]) cp_async4(&sbuf[cur ^ 1][tid + 256], fr + gg[2]);
        }
        cp_commit();

        u64_t aA = 0ull, aB = 0ull, aC = 0ull, aD = 0ull;
        {
            const float* sp_ = &sbuf[cur][kh * C1_CS + 2 * xp];
            #pragma unroll
            for (int r = 0; r < 6; ++r) {
                float2 f0 = *(const float2*)(sp_ + r * 20);
                float2 f1 = *(const float2*)(sp_ + r * 20 + 2);
                float2 f2 = *(const float2*)(sp_ + r * 20 + 4);
                u64_t vd[6];
                vd[0] = dup2(f0.x); vd[1] = dup2(f0.y);
                vd[2] = dup2(f1.x); vd[3] = dup2(f1.y);
                vd[4] = dup2(f2.x); vd[5] = dup2(f2.y);
                if (r < 5) {                       // y0: ky = r
                    #pragma unroll
                    for (int kx = 0; kx < 5; ++kx) {
                        aA = fma2(vd[kx],     wp[r * 5 + kx], aA);
                        aB = fma2(vd[kx + 1], wp[r * 5 + kx], aB);
                    }
                }
                if (r >= 1) {                      // y1: ky = r-1
                    #pragma unroll
                    for (int kx = 0; kx < 5; ++kx) {
                        aC = fma2(vd[kx],     wp[(r - 1) * 5 + kx], aC);
                        aD = fma2(vd[kx + 1], wp[(r - 1) * 5 + kx], aD);
                    }
                }
            }
        }
        // reduce-scatter over kh (lane bit3): kh0 keeps A,B; kh1 keeps C,D.
        u64_t kA = kh ? aC : aA;
        u64_t kB = kh ? aD : aB;
        u64_t sA = kh ? aA : aC;
        u64_t sB = kh ? aB : aD;
        kA = add2(kA, __shfl_xor_sync(0xffffffffu, sA, 8));
        kB = add2(kB, __shfl_xor_sync(0xffffffffu, sB, 8));

        u64_t spA = srm2_step_pk(st0, kA);
        u64_t spB = srm2_step_pk(st1, kB);
        u64_t part = add2(spA, spB);
        u64_t tot  = add2(part, __shfl_xor_sync(0xffffffffu, part, 8));
        u64_t up   = mul2(dup2(11.0f), tot);
        u64_t pp   = srm2_step_pk(stP, up);
        if (kh == 0) {
            float p0, p1; upk2(pp, p0, p1);
            g_s2[t * 32768 + outIdx]        = p0;
            g_s2[t * 32768 + outIdx + 2048] = p1;
        }

        cp_wait0();
        __syncthreads();
    }
}

// ---------------------------------------------------------------------------
// conv2 (3x3,pad1,16->32) + psp+spike + 2x2 pool + psp+spike, fused.
// R13 split: grid (hp=8, b=8, xq=4), 128 thr: xp = tid[0], kq = tid[1:2],
// co = tid>>3 (0..15; channels co & co+16 packed). Tile: 16ci x 4r x 6c,
// channel stride padded to 26 (kq offsets -> banks {0,8,16,24}).
// Reduce-scatter over kq (masks 2,4) + per-lane srm ownership.
// ---------------------------------------------------------------------------
#define C2_CS 26
__global__ void __launch_bounds__(128) conv2_fused_kernel(const float* __restrict__ W2) {
    __shared__ float sbuf[2][16 * C2_CS];  // [buf][ci*26 + r*6 + c]
    const int tid = threadIdx.x;
    const int xp  = tid & 1;
    const int kq  = (tid >> 1) & 3;
    const int co  = tid >> 3;             // 0..15 -> channels co, co+16
    const int hp  = blockIdx.x;           // 0..7
    const int b   = blockIdx.y;
    const int xq  = blockIdx.z;           // 0..3
    u64_t wp[36];
    #pragma unroll
    for (int k = 0; k < 36; ++k)
        wp[k] = pk2(W2[co * 144 + kq * 36 + k], W2[(co + 16) * 144 + kq * 36 + k]);
    for (int i = tid; i < 2 * 16 * C2_CS; i += 128) ((float*)sbuf)[i] = 0.f;

    // staging: slots tid + e*128, e = 0..3 (416 total)
    bool sv[4] = {false, false, false, false}; int gg[4] = {0, 0, 0, 0};
    #pragma unroll
    for (int e = 0; e < 4; ++e) {
        int i = tid + e * 128;
        if (i >= 16 * C2_CS) break;
        int ci = i / C2_CS, rem = i - ci * C2_CS;
        if (rem < 24) {
            int r = rem / 6, c = rem - r * 6;
            int row = 2 * hp + r - 1, col = xq * 4 + c - 1;
            if (row >= 0 && row < 16 && col >= 0 && col < 16) {
                sv[e] = true; gg[e] = b * 4096 + ci * 256 + row * 16 + col;
            }
        }
    }
    __syncthreads();

    if (sv[0]) cp_async4(&sbuf[0][tid],       g_s2 + gg[0]);
    if (sv[1]) cp_async4(&sbuf[0][tid + 128], g_s2 + gg[1]);
    if (sv[2]) cp_async4(&sbuf[0][tid + 256], g_s2 + gg[2]);
    if (sv[3]) cp_async4(&sbuf[0][tid + 384], g_s2 + gg[3]);
    cp_commit(); cp_wait0();
    __syncthreads();

    Srm2 st = {0,0,0,0}, stP = {0,0,0,0};
    const int outIdx = ((b * 32 + co) * 8 + hp) * 8 + xq * 2 + xp;  // ch1 +1024

    #pragma unroll 1
    for (int t = 0; t < T_STEPS; ++t) {
        const int cur = t & 1;
        if (t + 1 < T_STEPS) {
            const float* fr = g_s2 + (t + 1) * 32768;
            if (sv[0]) cp_async4(&sbuf[cur ^ 1][tid],       fr + gg[0]);
            if (sv[1]) cp_async4(&sbuf[cur ^ 1][tid + 128], fr + gg[1]);
            if (sv[2]) cp_async4(&sbuf[cur ^ 1][tid + 256], fr + gg[2]);
            if (sv[3]) cp_async4(&sbuf[cur ^ 1][tid + 384], fr + gg[3]);
        }
        cp_commit();

        u64_t aA = 0ull, aB = 0ull, aC = 0ull, aD = 0ull;
        #pragma unroll
        for (int lci = 0; lci < 4; ++lci) {
            const float* sp_ = &sbuf[cur][(kq * 4 + lci) * C2_CS + 2 * xp];
            #pragma unroll
            for (int r = 0; r < 4; ++r) {
                float2 f0 = *(const float2*)(sp_ + r * 6);
                float2 f1 = *(const float2*)(sp_ + r * 6 + 2);
                u64_t vd[4];
                vd[0] = dup2(f0.x); vd[1] = dup2(f0.y);
                vd[2] = dup2(f1.x); vd[3] = dup2(f1.y);
                if (r < 3) {                       // y0: ky = r
                    #pragma unroll
                    for (int kx = 0; kx < 3; ++kx) {
                        aA = fma2(vd[kx],     wp[lci * 9 + r * 3 + kx], aA);
                        aB = fma2(vd[kx + 1], wp[lci * 9 + r * 3 + kx], aB);
                    }
                }
                if (r >= 1) {                      // y1: ky = r-1
                    #pragma unroll
                    for (int kx = 0; kx < 3; ++kx) {
                        aC = fma2(vd[kx],     wp[lci * 9 + (r - 1) * 3 + kx], aC);
                        aD = fma2(vd[kx + 1], wp[lci * 9 + (r - 1) * 3 + kx], aD);
                    }
                }
            }
        }
        // reduce-scatter over kq (lane bits 1,2): lane kq owns quad neuron kq.
        u64_t k0 = (kq & 1) ? aB : aA;
        u64_t k1 = (kq & 1) ? aD : aC;
        u64_t s0 = (kq & 1) ? aA : aB;
        u64_t s1 = (kq & 1) ? aC : aD;
        k0 = add2(k0, __shfl_xor_sync(0xffffffffu, s0, 2));
        k1 = add2(k1, __shfl_xor_sync(0xffffffffu, s1, 2));
        u64_t kk = (kq & 2) ? k1 : k0;
        u64_t ss = (kq & 2) ? k0 : k1;
        kk = add2(kk, __shfl_xor_sync(0xffffffffu, ss, 4));

        u64_t sp = srm2_step_pk(st, kk);
        u64_t r1 = add2(sp, __shfl_xor_sync(0xffffffffu, sp, 2));
        u64_t tot = add2(r1, __shfl_xor_sync(0xffffffffu, r1, 4));
        u64_t up = mul2(dup2(11.0f), tot);
        u64_t pp = srm2_step_pk(stP, up);
        if (kq == 0) {
            float p0, p1; upk2(pp, p0, p1);
            g_s4[t * 16384 + outIdx]        = p0;
            g_s4[t * 16384 + outIdx + 1024] = p1;
        }

        cp_wait0();
        __syncthreads();
    }
}

// ---------------------------------------------------------------------------
// fc1 GEMM: rows=(t,b) 2400, K=2048, N=512. 64x64 tile, 4x4 micro, kc=32,
// register double-buffered global loads, FFMA2 inner loop (bit-exact).
// ---------------------------------------------------------------------------
__global__ void __launch_bounds__(256) fc1_gemm_kernel(const float* __restrict__ Wf1) {
    __shared__ float As[32 * 68];
    __shared__ float Bs[32 * 68];
    const int tid = threadIdx.x;
    const int txn = tid & 15, tym = tid >> 4;
    const int m0 = blockIdx.x * 64, n0 = blockIdx.y * 64;
    u64_t acc2[4][2];
    #pragma unroll
    for (int i = 0; i < 4; ++i) { acc2[i][0] = 0ull; acc2[i][1] = 0ull; }

    float4 ra[2], rb[2];
    #pragma unroll
    for (int e = 0; e < 2; ++e) {
        int i = tid + e * 256, m = i >> 3, kq = i & 7, row = m0 + m;
        ra[e] = (row < 2400) ? *(const float4*)(g_s4 + row * 2048 + kq * 4)
                             : make_float4(0.f, 0.f, 0.f, 0.f);
        rb[e] = *(const float4*)(Wf1 + (n0 + m) * 2048 + kq * 4);
    }

    for (int kb = 0; kb < 2048; kb += 32) {
        #pragma unroll
        for (int e = 0; e < 2; ++e) {
            int i = tid + e * 256, m = i >> 3, kq = i & 7;
            As[(kq * 4 + 0) * 68 + m] = ra[e].x;
            As[(kq * 4 + 1) * 68 + m] = ra[e].y;
            As[(kq * 4 + 2) * 68 + m] = ra[e].z;
            As[(kq * 4 + 3) * 68 + m] = ra[e].w;
            Bs[(kq * 4 + 0) * 68 + m] = rb[e].x;
            Bs[(kq * 4 + 1) * 68 + m] = rb[e].y;
            Bs[(kq * 4 + 2) * 68 + m] = rb[e].z;
            Bs[(kq * 4 + 3) * 68 + m] = rb[e].w;
        }
        __syncthreads();
        if (kb + 32 < 2048) {
            #pragma unroll
            for (int e = 0; e < 2; ++e) {
                int i = tid + e * 256, m = i >> 3, kq = i & 7, row = m0 + m;
                ra[e] = (row < 2400) ? *(const float4*)(g_s4 + row * 2048 + kb + 32 + kq * 4)
                                     : make_float4(0.f, 0.f, 0.f, 0.f);
                rb[e] = *(const float4*)(Wf1 + (n0 + m) * 2048 + kb + 32 + kq * 4);
            }
        }
        #pragma unroll
        for (int k = 0; k < 32; ++k) {
            float4 aq = *(const float4*)&As[k * 68 + tym * 4];
            float4 bq = *(const float4*)&Bs[k * 68 + txn * 4];
            u64_t b01 = pk2(bq.x, bq.y);
            u64_t b23 = pk2(bq.z, bq.w);
            float av[4] = {aq.x, aq.y, aq.z, aq.w};
            #pragma unroll
            for (int i = 0; i < 4; ++i) {
                u64_t ai = dup2(av[i]);
                acc2[i][0] = fma2(ai, b01, acc2[i][0]);
                acc2[i][1] = fma2(ai, b23, acc2[i][1]);
            }
        }
        __syncthreads();
    }
    #pragma unroll
    for (int i = 0; i < 4; ++i) {
        int row = m0 + tym * 4 + i;
        if (row < 2400) {
            float4 v;
            upk2(acc2[i][0], v.x, v.y);
            upk2(acc2[i][1], v.z, v.w);
            *(float4*)(g_u5 + row * 512 + n0 + txn * 4) = v;
        }
    }
}

// ---------------------------------------------------------------------------
__global__ void fc2_kernel(const float* __restrict__ Wf2) {
    int idx = blockIdx.x * 256 + threadIdx.x;
    if (idx >= 2400 * 11) return;
    int row = idx / 11, o = idx % 11;
    const float* a  = g_u5 + row * 512;
    const float* wv = Wf2 + o * 512;
    float acc = 0.f;
    #pragma unroll 8
    for (int c = 0; c < 512; ++c) acc = fmaf(a[c], wv[c], acc);
    g_u6[idx] = acc;
}

__global__ void final_scan_kernel(float* __restrict__ out) {
    int n = threadIdx.x;
    if (n >= 88) return;
    Srm st = {0.f, 0.f, 0.f, 0.f};
    #pragma unroll 1
    for (int t = 0; t < T_STEPS; ++t) {
        float s = srm_step(st, g_u6[t * 88 + n]);
        out[n * 300 + t] = s;
    }
}

// ---------------------------------------------------------------------------
extern "C" void kernel_launch(void* const* d_in, const int* in_sizes, int n_in,
                              void* d_out, int out_size) {
    (void)in_sizes; (void)n_in; (void)out_size;
    const float* s_in = (const float*)d_in[0];
    const float* W1   = (const float*)d_in[1];
    const float* W2   = (const float*)d_in[2];
    const float* Wf1  = (const float*)d_in[3];
    const float* Wf2  = (const float*)d_in[4];
    float* out = (float*)d_out;

    pool0_transpose_kernel<<<dim3(3, 512), dim3(32, 8)>>>(s_in);
    scan_s0_kernel<<<128, 64>>>();
    conv1_fused_kernel<<<dim3(16, 8, 2), 128>>>(W1);
    conv2_fused_kernel<<<dim3(8, 8, 4), 128>>>(W2);
    fc1_gemm_kernel<<<dim3(38, 8), 256>>>(Wf1);
    scan_u5_kernel<<<32, 64>>>();
    fc2_kernel<<<104, 256>>>(Wf2);
    final_scan_kernel<<<1, 128>>>(out);
}

// round 15
// speedup vs baseline: 1.0697x; 1.0697x over previous
#include <cuda_runtime.h>

// ---------------------------------------------------------------------------
// SLAYER SRM-alpha SNN forward, t-major layout [t*N + n].
// R14: conv1 reverted to R12 (256-thr, measured-best); conv2 keeps R13 split
// (256 blocks x 128 thr, measured 189us); final_scan stages g_u6 in smem.
// ---------------------------------------------------------------------------

#define T_STEPS 300

__device__ float g_s0[16384 * T_STEPS];   // pool0 potentials -> spikes (B,2,32,32)
__device__ float g_s2[32768 * T_STEPS];   // pool1 spikes (B,16,16,16)
__device__ float g_s4[16384 * T_STEPS];   // pool2 spikes (B,32,8,8)
__device__ float g_u5[4096  * T_STEPS];   // fc1 potentials -> spikes in place
__device__ float g_u6[88    * T_STEPS];   // fc2 potentials

typedef unsigned long long u64_t;

// ---- fp32x2 packed helpers --------------------------------------------------
__device__ __forceinline__ u64_t pk2(float lo, float hi) {
    u64_t r; asm("mov.b64 %0,{%1,%2};" : "=l"(r) : "f"(lo), "f"(hi)); return r;
}
__device__ __forceinline__ u64_t dup2(float x) {
    u64_t r; asm("mov.b64 %0,{%1,%1};" : "=l"(r) : "f"(x)); return r;
}
__device__ __forceinline__ void upk2(u64_t v, float& lo, float& hi) {
    asm("mov.b64 {%0,%1},%2;" : "=f"(lo), "=f"(hi) : "l"(v));
}
__device__ __forceinline__ u64_t fma2(u64_t a, u64_t b, u64_t c) {
    u64_t d; asm("fma.rn.f32x2 %0,%1,%2,%3;" : "=l"(d) : "l"(a), "l"(b), "l"(c)); return d;
}
__device__ __forceinline__ u64_t mul2(u64_t a, u64_t b) {
    u64_t d; asm("mul.rn.f32x2 %0,%1,%2;" : "=l"(d) : "l"(a), "l"(b)); return d;
}
__device__ __forceinline__ u64_t add2(u64_t a, u64_t b) {
    u64_t d; asm("add.rn.f32x2 %0,%1,%2;" : "=l"(d) : "l"(a), "l"(b)); return d;
}

// ---- SRM constants ----------------------------------------------------------
#define SRM_D  0.36787944117144233f   // exp(-1)
#define SRM_CE 2.7182818284590452f    // e
#define SRM_CR -54.365636569180905f   // -2*theta*e

struct Srm { float p1, q1, p2, q2; };

__device__ __forceinline__ float srm_step(Srm& s, float u) {
    s.q1 = __fmul_rn(SRM_D, __fadd_rn(s.q1, s.p1));
    s.p1 = __fadd_rn(__fmul_rn(SRM_D, s.p1), u);
    float y = __fmul_rn(SRM_CE, s.q1);
    s.q2 = __fmul_rn(SRM_D, __fadd_rn(s.q2, s.p2));
    float sp = (__fadd_rn(y, __fmul_rn(SRM_CR, s.q2)) >= 10.0f) ? 1.0f : 0.0f;
    s.p2 = __fadd_rn(__fmul_rn(SRM_D, s.p2), sp);
    return sp;
}

struct Srm2 { u64_t p1, q1, p2, q2; };

__device__ __forceinline__ void srm2_step(Srm2& s, u64_t u, float& slo, float& shi) {
    const u64_t D2  = dup2(SRM_D);
    const u64_t CE2 = dup2(SRM_CE);
    const u64_t CR2 = dup2(SRM_CR);
    s.q1 = mul2(D2, add2(s.q1, s.p1));
    s.p1 = add2(mul2(D2, s.p1), u);
    u64_t y = mul2(CE2, s.q1);
    s.q2 = mul2(D2, add2(s.q2, s.p2));
    u64_t m = add2(y, mul2(CR2, s.q2));
    float mlo, mhi; upk2(m, mlo, mhi);
    slo = (mlo >= 10.0f) ? 1.0f : 0.0f;
    shi = (mhi >= 10.0f) ? 1.0f : 0.0f;
    s.p2 = add2(mul2(D2, s.p2), pk2(slo, shi));
}

__device__ __forceinline__ u64_t srm2_step_pk(Srm2& s, u64_t u) {
    float slo, shi;
    srm2_step(s, u, slo, shi);
    return pk2(slo, shi);
}

__device__ __forceinline__ void cp_async4(void* sm, const void* gm) {
    unsigned s = (unsigned)__cvta_generic_to_shared(sm);
    asm volatile("cp.async.ca.shared.global [%0], [%1], 4;" :: "r"(s), "l"(gm));
}
__device__ __forceinline__ void cp_commit() { asm volatile("cp.async.commit_group;"); }
__device__ __forceinline__ void cp_wait0()  { asm volatile("cp.async.wait_group 0;" ::: "memory"); }

// ---------------------------------------------------------------------------
// K0: 4x4 sum-pool (gain 11) + transpose (B,2,128,128,T) -> t-major g_s0.
// ---------------------------------------------------------------------------
__global__ void pool0_transpose_kernel(const float* __restrict__ x) {
    __shared__ float sm[128][33];
    const int tx = threadIdx.x, ty = threadIdx.y;
    const int tb = blockIdx.x;
    const int nb = blockIdx.y;
    const int ho = nb & 31, bc = nb >> 5;
    const int tq = tb * 32 + tx;
    if (tq < 75) {
        const float* base = x + (size_t)((bc * 128 + ho * 4) * 128) * 300 + tq * 4;
        for (int j = ty; j < 32; j += 8) {
            float ax = 0.f, ay = 0.f, az = 0.f, aw = 0.f;
            #pragma unroll
            for (int dy = 0; dy < 4; ++dy) {
                const float* rp = base + (size_t)(dy * 128 + j * 4) * 300;
                float4 v0 = *(const float4*)(rp);
                float4 v1 = *(const float4*)(rp + 300);
                float4 v2 = *(const float4*)(rp + 600);
                float4 v3 = *(const float4*)(rp + 900);
                ax += ((v0.x + v1.x) + v2.x) + v3.x;
                ay += ((v0.y + v1.y) + v2.y) + v3.y;
                az += ((v0.z + v1.z) + v2.z) + v3.z;
                aw += ((v0.w + v1.w) + v2.w) + v3.w;
            }
            sm[tx * 4 + 0][j] = 11.0f * ax;
            sm[tx * 4 + 1][j] = 11.0f * ay;
            sm[tx * 4 + 2][j] = 11.0f * az;
            sm[tx * 4 + 3][j] = 11.0f * aw;
        }
    }
    __syncthreads();
    for (int tt = ty; tt < 128; tt += 8) {
        int t2 = tb * 128 + tt;
        if (t2 < T_STEPS)
            g_s0[t2 * 16384 + nb * 32 + tx] = sm[tt][tx];
    }
}

// ---- packed in-place psp+spike scan (2 neurons/thread, manual prefetch) ----
__device__ __forceinline__ void scan_body2(float* buf, int N) {
    int n2 = blockIdx.x * blockDim.x + threadIdx.x;
    if (n2 >= N / 2) return;
    Srm2 st = {0, 0, 0, 0};
    float* p = buf + 2 * n2;
    float2 v = *(float2*)p;
    #pragma unroll 1
    for (int t = 0; t < T_STEPS; ++t) {
        float2 vn = v;
        if (t + 1 < T_STEPS) vn = *(float2*)(p + (t + 1) * N);
        float slo, shi;
        srm2_step(st, pk2(v.x, v.y), slo, shi);
        *(float2*)(p + t * N) = make_float2(slo, shi);
        v = vn;
    }
}
__global__ void scan_s0_kernel() { scan_body2(g_s0, 16384); }
__global__ void scan_u5_kernel() { scan_body2(g_u5, 4096); }

// ---------------------------------------------------------------------------
// conv1 (5x5,pad2,2->16) + psp+spike + 2x2 pool + psp+spike, fused. (R12 ver.)
// grid (hp=16, b=8), 256 thr: xp = tid[0:3], kh = tid[4], co = tid>>5 (0..7).
// Channels co & co+8 f32x2-packed. Reduce-scatter over kh (mask 16) +
// per-lane srm ownership (kh0 owns A,B; kh1 owns C,D).
// ---------------------------------------------------------------------------
__global__ void __launch_bounds__(256) conv1_fused_kernel(const float* __restrict__ W1) {
    __shared__ float sbuf[2][432];        // [buf][ci*216 + r*36 + c], rows 2hp-2..2hp+3
    const int tid = threadIdx.x;
    const int xp  = tid & 15;
    const int kh  = (tid >> 4) & 1;
    const int co  = tid >> 5;             // 0..7 -> channels co, co+8
    const int hp  = blockIdx.x;
    const int b   = blockIdx.y;
    u64_t wp[25];
    #pragma unroll
    for (int k = 0; k < 25; ++k)
        wp[k] = pk2(W1[co * 50 + kh * 25 + k], W1[(co + 8) * 50 + kh * 25 + k]);
    for (int i = tid; i < 864; i += 256) ((float*)sbuf)[i] = 0.f;

    bool sv0 = false, sv1 = false; int g0 = 0, g1 = 0;
    {
        int i = tid;
        int ci = i / 216, rem = i - ci * 216, r = rem / 36, c = rem - r * 36;
        int row = 2 * hp + r - 2, col = c - 2;
        if (row >= 0 && row < 32 && col >= 0 && col < 32) {
            sv0 = true; g0 = b * 2048 + ci * 1024 + row * 32 + col;
        }
    }
    if (tid + 256 < 432) {
        int i = tid + 256;
        int ci = i / 216, rem = i - ci * 216, r = rem / 36, c = rem - r * 36;
        int row = 2 * hp + r - 2, col = c - 2;
        if (row >= 0 && row < 32 && col >= 0 && col < 32) {
            sv1 = true; g1 = b * 2048 + ci * 1024 + row * 32 + col;
        }
    }
    __syncthreads();

    if (sv0) cp_async4(&sbuf[0][tid],       g_s0 + g0);
    if (sv1) cp_async4(&sbuf[0][tid + 256], g_s0 + g1);
    cp_commit(); cp_wait0();
    __syncthreads();

    Srm2 st0 = {0,0,0,0}, st1 = {0,0,0,0}, stP = {0,0,0,0};
    const int outIdx = ((b * 16 + co) * 16 + hp) * 16 + xp;   // ch1 at +2048

    #pragma unroll 1
    for (int t = 0; t < T_STEPS; ++t) {
        const int cur = t & 1;
        if (t + 1 < T_STEPS) {
            const float* fr = g_s0 + (t + 1) * 16384;
            if (sv0) cp_async4(&sbuf[cur ^ 1][tid],       fr + g0);
            if (sv1) cp_async4(&sbuf[cur ^ 1][tid + 256], fr + g1);
        }
        cp_commit();

        u64_t aA = 0ull, aB = 0ull, aC = 0ull, aD = 0ull;
        {
            const float* sp_ = &sbuf[cur][kh * 216 + 2 * xp];
            #pragma unroll
            for (int r = 0; r < 6; ++r) {
                float2 f0 = *(const float2*)(sp_ + r * 36);
                float2 f1 = *(const float2*)(sp_ + r * 36 + 2);
                float2 f2 = *(const float2*)(sp_ + r * 36 + 4);
                u64_t vd[6];
                vd[0] = dup2(f0.x); vd[1] = dup2(f0.y);
                vd[2] = dup2(f1.x); vd[3] = dup2(f1.y);
                vd[4] = dup2(f2.x); vd[5] = dup2(f2.y);
                if (r < 5) {                       // y0: ky = r
                    #pragma unroll
                    for (int kx = 0; kx < 5; ++kx) {
                        aA = fma2(vd[kx],     wp[r * 5 + kx], aA);
                        aB = fma2(vd[kx + 1], wp[r * 5 + kx], aB);
                    }
                }
                if (r >= 1) {                      // y1: ky = r-1
                    #pragma unroll
                    for (int kx = 0; kx < 5; ++kx) {
                        aC = fma2(vd[kx],     wp[(r - 1) * 5 + kx], aC);
                        aD = fma2(vd[kx + 1], wp[(r - 1) * 5 + kx], aD);
                    }
                }
            }
        }
        // reduce-scatter over kh: kh0 keeps A,B; kh1 keeps C,D. Bit-exact.
        u64_t kA = kh ? aC : aA;
        u64_t kB = kh ? aD : aB;
        u64_t sA = kh ? aA : aC;
        u64_t sB = kh ? aB : aD;
        kA = add2(kA, __shfl_xor_sync(0xffffffffu, sA, 16));
        kB = add2(kB, __shfl_xor_sync(0xffffffffu, sB, 16));

        u64_t spA = srm2_step_pk(st0, kA);
        u64_t spB = srm2_step_pk(st1, kB);
        u64_t part = add2(spA, spB);
        u64_t tot  = add2(part, __shfl_xor_sync(0xffffffffu, part, 16));
        u64_t up   = mul2(dup2(11.0f), tot);
        u64_t pp   = srm2_step_pk(stP, up);
        if (kh == 0) {
            float p0, p1; upk2(pp, p0, p1);
            g_s2[t * 32768 + outIdx]        = p0;
            g_s2[t * 32768 + outIdx + 2048] = p1;
        }

        cp_wait0();
        __syncthreads();
    }
}

// ---------------------------------------------------------------------------
// conv2 (3x3,pad1,16->32) + psp+spike + 2x2 pool + psp+spike, fused. (R13 ver.)
// grid (hp=8, b=8, xq=4), 128 thr: xp = tid[0], kq = tid[1:2], co = tid>>3
// (0..15; channels co & co+16 packed). Tile: 16ci x 4r x 6c, CS=26
// (kq offsets -> banks {0,8,16,24}). Reduce-scatter over kq (masks 2,4).
// ---------------------------------------------------------------------------
#define C2_CS 26
__global__ void __launch_bounds__(128) conv2_fused_kernel(const float* __restrict__ W2) {
    __shared__ float sbuf[2][16 * C2_CS];  // [buf][ci*26 + r*6 + c]
    const int tid = threadIdx.x;
    const int xp  = tid & 1;
    const int kq  = (tid >> 1) & 3;
    const int co  = tid >> 3;             // 0..15 -> channels co, co+16
    const int hp  = blockIdx.x;           // 0..7
    const int b   = blockIdx.y;
    const int xq  = blockIdx.z;           // 0..3
    u64_t wp[36];
    #pragma unroll
    for (int k = 0; k < 36; ++k)
        wp[k] = pk2(W2[co * 144 + kq * 36 + k], W2[(co + 16) * 144 + kq * 36 + k]);
    for (int i = tid; i < 2 * 16 * C2_CS; i += 128) ((float*)sbuf)[i] = 0.f;

    bool sv[4] = {false, false, false, false}; int gg[4] = {0, 0, 0, 0};
    #pragma unroll
    for (int e = 0; e < 4; ++e) {
        int i = tid + e * 128;
        if (i >= 16 * C2_CS) break;
        int ci = i / C2_CS, rem = i - ci * C2_CS;
        if (rem < 24) {
            int r = rem / 6, c = rem - r * 6;
            int row = 2 * hp + r - 1, col = xq * 4 + c - 1;
            if (row >= 0 && row < 16 && col >= 0 && col < 16) {
                sv[e] = true; gg[e] = b * 4096 + ci * 256 + row * 16 + col;
            }
        }
    }
    __syncthreads();

    if (sv[0]) cp_async4(&sbuf[0][tid],       g_s2 + gg[0]);
    if (sv[1]) cp_async4(&sbuf[0][tid + 128], g_s2 + gg[1]);
    if (sv[2]) cp_async4(&sbuf[0][tid + 256], g_s2 + gg[2]);
    if (sv[3]) cp_async4(&sbuf[0][tid + 384], g_s2 + gg[3]);
    cp_commit(); cp_wait0();
    __syncthreads();

    Srm2 st = {0,0,0,0}, stP = {0,0,0,0};
    const int outIdx = ((b * 32 + co) * 8 + hp) * 8 + xq * 2 + xp;  // ch1 +1024

    #pragma unroll 1
    for (int t = 0; t < T_STEPS; ++t) {
        const int cur = t & 1;
        if (t + 1 < T_STEPS) {
            const float* fr = g_s2 + (t + 1) * 32768;
            if (sv[0]) cp_async4(&sbuf[cur ^ 1][tid],       fr + gg[0]);
            if (sv[1]) cp_async4(&sbuf[cur ^ 1][tid + 128], fr + gg[1]);
            if (sv[2]) cp_async4(&sbuf[cur ^ 1][tid + 256], fr + gg[2]);
            if (sv[3]) cp_async4(&sbuf[cur ^ 1][tid + 384], fr + gg[3]);
        }
        cp_commit();

        u64_t aA = 0ull, aB = 0ull, aC = 0ull, aD = 0ull;
        #pragma unroll
        for (int lci = 0; lci < 4; ++lci) {
            const float* sp_ = &sbuf[cur][(kq * 4 + lci) * C2_CS + 2 * xp];
            #pragma unroll
            for (int r = 0; r < 4; ++r) {
                float2 f0 = *(const float2*)(sp_ + r * 6);
                float2 f1 = *(const float2*)(sp_ + r * 6 + 2);
                u64_t vd[4];
                vd[0] = dup2(f0.x); vd[1] = dup2(f0.y);
                vd[2] = dup2(f1.x); vd[3] = dup2(f1.y);
                if (r < 3) {                       // y0: ky = r
                    #pragma unroll
                    for (int kx = 0; kx < 3; ++kx) {
                        aA = fma2(vd[kx],     wp[lci * 9 + r * 3 + kx], aA);
                        aB = fma2(vd[kx + 1], wp[lci * 9 + r * 3 + kx], aB);
                    }
                }
                if (r >= 1) {                      // y1: ky = r-1
                    #pragma unroll
                    for (int kx = 0; kx < 3; ++kx) {
                        aC = fma2(vd[kx],     wp[lci * 9 + (r - 1) * 3 + kx], aC);
                        aD = fma2(vd[kx + 1], wp[lci * 9 + (r - 1) * 3 + kx], aD);
                    }
                }
            }
        }
        // reduce-scatter over kq (lane bits 1,2): lane kq owns quad neuron kq.
        u64_t k0 = (kq & 1) ? aB : aA;
        u64_t k1 = (kq & 1) ? aD : aC;
        u64_t s0 = (kq & 1) ? aA : aB;
        u64_t s1 = (kq & 1) ? aC : aD;
        k0 = add2(k0, __shfl_xor_sync(0xffffffffu, s0, 2));
        k1 = add2(k1, __shfl_xor_sync(0xffffffffu, s1, 2));
        u64_t kk = (kq & 2) ? k1 : k0;
        u64_t ss = (kq & 2) ? k0 : k1;
        kk = add2(kk, __shfl_xor_sync(0xffffffffu, ss, 4));

        u64_t sp = srm2_step_pk(st, kk);
        u64_t r1 = add2(sp, __shfl_xor_sync(0xffffffffu, sp, 2));
        u64_t tot = add2(r1, __shfl_xor_sync(0xffffffffu, r1, 4));
        u64_t up = mul2(dup2(11.0f), tot);
        u64_t pp = srm2_step_pk(stP, up);
        if (kq == 0) {
            float p0, p1; upk2(pp, p0, p1);
            g_s4[t * 16384 + outIdx]        = p0;
            g_s4[t * 16384 + outIdx + 1024] = p1;
        }

        cp_wait0();
        __syncthreads();
    }
}

// ---------------------------------------------------------------------------
// fc1 GEMM: rows=(t,b) 2400, K=2048, N=512. 64x64 tile, 4x4 micro, kc=32,
// register double-buffered global loads, FFMA2 inner loop (bit-exact).
// ---------------------------------------------------------------------------
__global__ void __launch_bounds__(256) fc1_gemm_kernel(const float* __restrict__ Wf1) {
    __shared__ float As[32 * 68];
    __shared__ float Bs[32 * 68];
    const int tid = threadIdx.x;
    const int txn = tid & 15, tym = tid >> 4;
    const int m0 = blockIdx.x * 64, n0 = blockIdx.y * 64;
    u64_t acc2[4][2];
    #pragma unroll
    for (int i = 0; i < 4; ++i) { acc2[i][0] = 0ull; acc2[i][1] = 0ull; }

    float4 ra[2], rb[2];
    #pragma unroll
    for (int e = 0; e < 2; ++e) {
        int i = tid + e * 256, m = i >> 3, kq = i & 7, row = m0 + m;
        ra[e] = (row < 2400) ? *(const float4*)(g_s4 + row * 2048 + kq * 4)
                             : make_float4(0.f, 0.f, 0.f, 0.f);
        rb[e] = *(const float4*)(Wf1 + (n0 + m) * 2048 + kq * 4);
    }

    for (int kb = 0; kb < 2048; kb += 32) {
        #pragma unroll
        for (int e = 0; e < 2; ++e) {
            int i = tid + e * 256, m = i >> 3, kq = i & 7;
            As[(kq * 4 + 0) * 68 + m] = ra[e].x;
            As[(kq * 4 + 1) * 68 + m] = ra[e].y;
            As[(kq * 4 + 2) * 68 + m] = ra[e].z;
            As[(kq * 4 + 3) * 68 + m] = ra[e].w;
            Bs[(kq * 4 + 0) * 68 + m] = rb[e].x;
            Bs[(kq * 4 + 1) * 68 + m] = rb[e].y;
            Bs[(kq * 4 + 2) * 68 + m] = rb[e].z;
            Bs[(kq * 4 + 3) * 68 + m] = rb[e].w;
        }
        __syncthreads();
        if (kb + 32 < 2048) {
            #pragma unroll
            for (int e = 0; e < 2; ++e) {
                int i = tid + e * 256, m = i >> 3, kq = i & 7, row = m0 + m;
                ra[e] = (row < 2400) ? *(const float4*)(g_s4 + row * 2048 + kb + 32 + kq * 4)
                                     : make_float4(0.f, 0.f, 0.f, 0.f);
                rb[e] = *(const float4*)(Wf1 + (n0 + m) * 2048 + kb + 32 + kq * 4);
            }
        }
        #pragma unroll
        for (int k = 0; k < 32; ++k) {
            float4 aq = *(const float4*)&As[k * 68 + tym * 4];
            float4 bq = *(const float4*)&Bs[k * 68 + txn * 4];
            u64_t b01 = pk2(bq.x, bq.y);
            u64_t b23 = pk2(bq.z, bq.w);
            float av[4] = {aq.x, aq.y, aq.z, aq.w};
            #pragma unroll
            for (int i = 0; i < 4; ++i) {
                u64_t ai = dup2(av[i]);
                acc2[i][0] = fma2(ai, b01, acc2[i][0]);
                acc2[i][1] = fma2(ai, b23, acc2[i][1]);
            }
        }
        __syncthreads();
    }
    #pragma unroll
    for (int i = 0; i < 4; ++i) {
        int row = m0 + tym * 4 + i;
        if (row < 2400) {
            float4 v;
            upk2(acc2[i][0], v.x, v.y);
            upk2(acc2[i][1], v.z, v.w);
            *(float4*)(g_u5 + row * 512 + n0 + txn * 4) = v;
        }
    }
}

// ---------------------------------------------------------------------------
__global__ void fc2_kernel(const float* __restrict__ Wf2) {
    int idx = blockIdx.x * 256 + threadIdx.x;
    if (idx >= 2400 * 11) return;
    int row = idx / 11, o = idx % 11;
    const float* a  = g_u5 + row * 512;
    const float* wv = Wf2 + o * 512;
    float acc = 0.f;
    #pragma unroll 8
    for (int c = 0; c < 512; ++c) acc = fmaf(a[c], wv[c], acc);
    g_u6[idx] = acc;
}

// final scan with g_u6 fully staged in shared memory (105.6 KB).
__global__ void final_scan_kernel(float* __restrict__ out) {
    extern __shared__ float su6[];        // 88*300 floats
    const int tid = threadIdx.x;
    for (int i = tid; i < 88 * T_STEPS; i += 128)
        su6[i] = g_u6[i];
    __syncthreads();
    int n = tid;
    if (n >= 88) return;
    Srm st = {0.f, 0.f, 0.f, 0.f};
    #pragma unroll 1
    for (int t = 0; t < T_STEPS; ++t) {
        float s = srm_step(st, su6[t * 88 + n]);
        out[n * 300 + t] = s;
    }
}

// ---------------------------------------------------------------------------
extern "C" void kernel_launch(void* const* d_in, const int* in_sizes, int n_in,
                              void* d_out, int out_size) {
    (void)in_sizes; (void)n_in; (void)out_size;
    const float* s_in = (const float*)d_in[0];
    const float* W1   = (const float*)d_in[1];
    const float* W2   = (const float*)d_in[2];
    const float* Wf1  = (const float*)d_in[3];
    const float* Wf2  = (const float*)d_in[4];
    float* out = (float*)d_out;

    pool0_transpose_kernel<<<dim3(3, 512), dim3(32, 8)>>>(s_in);
    scan_s0_kernel<<<128, 64>>>();
    conv1_fused_kernel<<<dim3(16, 8), 256>>>(W1);
    conv2_fused_kernel<<<dim3(8, 8, 4), 128>>>(W2);
    fc1_gemm_kernel<<<dim3(38, 8), 256>>>(Wf1);
    scan_u5_kernel<<<32, 64>>>();
    fc2_kernel<<<104, 256>>>(Wf2);
    cudaFuncSetAttribute(final_scan_kernel,
                         cudaFuncAttributeMaxDynamicSharedMemorySize,
                         88 * T_STEPS * (int)sizeof(float));
    final_scan_kernel<<<1, 128, 88 * T_STEPS * sizeof(float)>>>(out);
}

// round 16
// speedup vs baseline: 1.0815x; 1.0110x over previous
#include <cuda_runtime.h>

// ---------------------------------------------------------------------------
// SLAYER SRM-alpha SNN forward, t-major layout [t*N + n].
// R15: R14 core kept intact (conv1=R12, conv2=R13-split, fc1 FFMA2, smem
// final_scan). New: fc2 vectorized float4 (same accumulation chain) and
// standalone scans widened to 4 neurons/thread (2 independent srm2 chains).
// ---------------------------------------------------------------------------

#define T_STEPS 300

__device__ float g_s0[16384 * T_STEPS];   // pool0 potentials -> spikes (B,2,32,32)
__device__ float g_s2[32768 * T_STEPS];   // pool1 spikes (B,16,16,16)
__device__ float g_s4[16384 * T_STEPS];   // pool2 spikes (B,32,8,8)
__device__ float g_u5[4096  * T_STEPS];   // fc1 potentials -> spikes in place
__device__ float g_u6[88    * T_STEPS];   // fc2 potentials

typedef unsigned long long u64_t;

// ---- fp32x2 packed helpers --------------------------------------------------
__device__ __forceinline__ u64_t pk2(float lo, float hi) {
    u64_t r; asm("mov.b64 %0,{%1,%2};" : "=l"(r) : "f"(lo), "f"(hi)); return r;
}
__device__ __forceinline__ u64_t dup2(float x) {
    u64_t r; asm("mov.b64 %0,{%1,%1};" : "=l"(r) : "f"(x)); return r;
}
__device__ __forceinline__ void upk2(u64_t v, float& lo, float& hi) {
    asm("mov.b64 {%0,%1},%2;" : "=f"(lo), "=f"(hi) : "l"(v));
}
__device__ __forceinline__ u64_t fma2(u64_t a, u64_t b, u64_t c) {
    u64_t d; asm("fma.rn.f32x2 %0,%1,%2,%3;" : "=l"(d) : "l"(a), "l"(b), "l"(c)); return d;
}
__device__ __forceinline__ u64_t mul2(u64_t a, u64_t b) {
    u64_t d; asm("mul.rn.f32x2 %0,%1,%2;" : "=l"(d) : "l"(a), "l"(b)); return d;
}
__device__ __forceinline__ u64_t add2(u64_t a, u64_t b) {
    u64_t d; asm("add.rn.f32x2 %0,%1,%2;" : "=l"(d) : "l"(a), "l"(b)); return d;
}

// ---- SRM constants ----------------------------------------------------------
#define SRM_D  0.36787944117144233f   // exp(-1)
#define SRM_CE 2.7182818284590452f    // e
#define SRM_CR -54.365636569180905f   // -2*theta*e

struct Srm { float p1, q1, p2, q2; };

__device__ __forceinline__ float srm_step(Srm& s, float u) {
    s.q1 = __fmul_rn(SRM_D, __fadd_rn(s.q1, s.p1));
    s.p1 = __fadd_rn(__fmul_rn(SRM_D, s.p1), u);
    float y = __fmul_rn(SRM_CE, s.q1);
    s.q2 = __fmul_rn(SRM_D, __fadd_rn(s.q2, s.p2));
    float sp = (__fadd_rn(y, __fmul_rn(SRM_CR, s.q2)) >= 10.0f) ? 1.0f : 0.0f;
    s.p2 = __fadd_rn(__fmul_rn(SRM_D, s.p2), sp);
    return sp;
}

struct Srm2 { u64_t p1, q1, p2, q2; };

__device__ __forceinline__ void srm2_step(Srm2& s, u64_t u, float& slo, float& shi) {
    const u64_t D2  = dup2(SRM_D);
    const u64_t CE2 = dup2(SRM_CE);
    const u64_t CR2 = dup2(SRM_CR);
    s.q1 = mul2(D2, add2(s.q1, s.p1));
    s.p1 = add2(mul2(D2, s.p1), u);
    u64_t y = mul2(CE2, s.q1);
    s.q2 = mul2(D2, add2(s.q2, s.p2));
    u64_t m = add2(y, mul2(CR2, s.q2));
    float mlo, mhi; upk2(m, mlo, mhi);
    slo = (mlo >= 10.0f) ? 1.0f : 0.0f;
    shi = (mhi >= 10.0f) ? 1.0f : 0.0f;
    s.p2 = add2(mul2(D2, s.p2), pk2(slo, shi));
}

__device__ __forceinline__ u64_t srm2_step_pk(Srm2& s, u64_t u) {
    float slo, shi;
    srm2_step(s, u, slo, shi);
    return pk2(slo, shi);
}

__device__ __forceinline__ void cp_async4(void* sm, const void* gm) {
    unsigned s = (unsigned)__cvta_generic_to_shared(sm);
    asm volatile("cp.async.ca.shared.global [%0], [%1], 4;" :: "r"(s), "l"(gm));
}
__device__ __forceinline__ void cp_commit() { asm volatile("cp.async.commit_group;"); }
__device__ __forceinline__ void cp_wait0()  { asm volatile("cp.async.wait_group 0;" ::: "memory"); }

// ---------------------------------------------------------------------------
// K0: 4x4 sum-pool (gain 11) + transpose (B,2,128,128,T) -> t-major g_s0.
// ---------------------------------------------------------------------------
__global__ void pool0_transpose_kernel(const float* __restrict__ x) {
    __shared__ float sm[128][33];
    const int tx = threadIdx.x, ty = threadIdx.y;
    const int tb = blockIdx.x;
    const int nb = blockIdx.y;
    const int ho = nb & 31, bc = nb >> 5;
    const int tq = tb * 32 + tx;
    if (tq < 75) {
        const float* base = x + (size_t)((bc * 128 + ho * 4) * 128) * 300 + tq * 4;
        for (int j = ty; j < 32; j += 8) {
            float ax = 0.f, ay = 0.f, az = 0.f, aw = 0.f;
            #pragma unroll
            for (int dy = 0; dy < 4; ++dy) {
                const float* rp = base + (size_t)(dy * 128 + j * 4) * 300;
                float4 v0 = *(const float4*)(rp);
                float4 v1 = *(const float4*)(rp + 300);
                float4 v2 = *(const float4*)(rp + 600);
                float4 v3 = *(const float4*)(rp + 900);
                ax += ((v0.x + v1.x) + v2.x) + v3.x;
                ay += ((v0.y + v1.y) + v2.y) + v3.y;
                az += ((v0.z + v1.z) + v2.z) + v3.z;
                aw += ((v0.w + v1.w) + v2.w) + v3.w;
            }
            sm[tx * 4 + 0][j] = 11.0f * ax;
            sm[tx * 4 + 1][j] = 11.0f * ay;
            sm[tx * 4 + 2][j] = 11.0f * az;
            sm[tx * 4 + 3][j] = 11.0f * aw;
        }
    }
    __syncthreads();
    for (int tt = ty; tt < 128; tt += 8) {
        int t2 = tb * 128 + tt;
        if (t2 < T_STEPS)
            g_s0[t2 * 16384 + nb * 32 + tx] = sm[tt][tx];
    }
}

// ---- packed in-place psp+spike scan (4 neurons/thread, manual prefetch) ----
__device__ __forceinline__ void scan_body4(float* buf, int N) {
    int n4 = blockIdx.x * blockDim.x + threadIdx.x;
    if (n4 >= N / 4) return;
    Srm2 st0 = {0, 0, 0, 0}, st1 = {0, 0, 0, 0};
    float* p = buf + 4 * n4;
    float4 v = *(float4*)p;
    #pragma unroll 1
    for (int t = 0; t < T_STEPS; ++t) {
        float4 vn = v;
        if (t + 1 < T_STEPS) vn = *(float4*)(p + (t + 1) * N);  // prefetch
        float s0, s1, s2, s3;
        srm2_step(st0, pk2(v.x, v.y), s0, s1);
        srm2_step(st1, pk2(v.z, v.w), s2, s3);
        *(float4*)(p + t * N) = make_float4(s0, s1, s2, s3);
        v = vn;
    }
}
__global__ void scan_s0_kernel() { scan_body4(g_s0, 16384); }
__global__ void scan_u5_kernel() { scan_body4(g_u5, 4096); }

// ---------------------------------------------------------------------------
// conv1 (5x5,pad2,2->16) + psp+spike + 2x2 pool + psp+spike, fused. (R12 ver.)
// grid (hp=16, b=8), 256 thr: xp = tid[0:3], kh = tid[4], co = tid>>5 (0..7).
// Channels co & co+8 f32x2-packed. Reduce-scatter over kh (mask 16) +
// per-lane srm ownership (kh0 owns A,B; kh1 owns C,D).
// ---------------------------------------------------------------------------
__global__ void __launch_bounds__(256) conv1_fused_kernel(const float* __restrict__ W1) {
    __shared__ float sbuf[2][432];        // [buf][ci*216 + r*36 + c], rows 2hp-2..2hp+3
    const int tid = threadIdx.x;
    const int xp  = tid & 15;
    const int kh  = (tid >> 4) & 1;
    const int co  = tid >> 5;             // 0..7 -> channels co, co+8
    const int hp  = blockIdx.x;
    const int b   = blockIdx.y;
    u64_t wp[25];
    #pragma unroll
    for (int k = 0; k < 25; ++k)
        wp[k] = pk2(W1[co * 50 + kh * 25 + k], W1[(co + 8) * 50 + kh * 25 + k]);
    for (int i = tid; i < 864; i += 256) ((float*)sbuf)[i] = 0.f;

    bool sv0 = false, sv1 = false; int g0 = 0, g1 = 0;
    {
        int i = tid;
        int ci = i / 216, rem = i - ci * 216, r = rem / 36, c = rem - r * 36;
        int row = 2 * hp + r - 2, col = c - 2;
        if (row >= 0 && row < 32 && col >= 0 && col < 32) {
            sv0 = true; g0 = b * 2048 + ci * 1024 + row * 32 + col;
        }
    }
    if (tid + 256 < 432) {
        int i = tid + 256;
        int ci = i / 216, rem = i - ci * 216, r = rem / 36, c = rem - r * 36;
        int row = 2 * hp + r - 2, col = c - 2;
        if (row >= 0 && row < 32 && col >= 0 && col < 32) {
            sv1 = true; g1 = b * 2048 + ci * 1024 + row * 32 + col;
        }
    }
    __syncthreads();

    if (sv0) cp_async4(&sbuf[0][tid],       g_s0 + g0);
    if (sv1) cp_async4(&sbuf[0][tid + 256], g_s0 + g1);
    cp_commit(); cp_wait0();
    __syncthreads();

    Srm2 st0 = {0,0,0,0}, st1 = {0,0,0,0}, stP = {0,0,0,0};
    const int outIdx = ((b * 16 + co) * 16 + hp) * 16 + xp;   // ch1 at +2048

    #pragma unroll 1
    for (int t = 0; t < T_STEPS; ++t) {
        const int cur = t & 1;
        if (t + 1 < T_STEPS) {
            const float* fr = g_s0 + (t + 1) * 16384;
            if (sv0) cp_async4(&sbuf[cur ^ 1][tid],       fr + g0);
            if (sv1) cp_async4(&sbuf[cur ^ 1][tid + 256], fr + g1);
        }
        cp_commit();

        u64_t aA = 0ull, aB = 0ull, aC = 0ull, aD = 0ull;
        {
            const float* sp_ = &sbuf[cur][kh * 216 + 2 * xp];
            #pragma unroll
            for (int r = 0; r < 6; ++r) {
                float2 f0 = *(const float2*)(sp_ + r * 36);
                float2 f1 = *(const float2*)(sp_ + r * 36 + 2);
                float2 f2 = *(const float2*)(sp_ + r * 36 + 4);
                u64_t vd[6];
                vd[0] = dup2(f0.x); vd[1] = dup2(f0.y);
                vd[2] = dup2(f1.x); vd[3] = dup2(f1.y);
                vd[4] = dup2(f2.x); vd[5] = dup2(f2.y);
                if (r < 5) {                       // y0: ky = r
                    #pragma unroll
                    for (int kx = 0; kx < 5; ++kx) {
                        aA = fma2(vd[kx],     wp[r * 5 + kx], aA);
                        aB = fma2(vd[kx + 1], wp[r * 5 + kx], aB);
                    }
                }
                if (r >= 1) {                      // y1: ky = r-1
                    #pragma unroll
                    for (int kx = 0; kx < 5; ++kx) {
                        aC = fma2(vd[kx],     wp[(r - 1) * 5 + kx], aC);
                        aD = fma2(vd[kx + 1], wp[(r - 1) * 5 + kx], aD);
                    }
                }
            }
        }
        // reduce-scatter over kh: kh0 keeps A,B; kh1 keeps C,D. Bit-exact.
        u64_t kA = kh ? aC : aA;
        u64_t kB = kh ? aD : aB;
        u64_t sA = kh ? aA : aC;
        u64_t sB = kh ? aB : aD;
        kA = add2(kA, __shfl_xor_sync(0xffffffffu, sA, 16));
        kB = add2(kB, __shfl_xor_sync(0xffffffffu, sB, 16));

        u64_t spA = srm2_step_pk(st0, kA);
        u64_t spB = srm2_step_pk(st1, kB);
        u64_t part = add2(spA, spB);
        u64_t tot  = add2(part, __shfl_xor_sync(0xffffffffu, part, 16));
        u64_t up   = mul2(dup2(11.0f), tot);
        u64_t pp   = srm2_step_pk(stP, up);
        if (kh == 0) {
            float p0, p1; upk2(pp, p0, p1);
            g_s2[t * 32768 + outIdx]        = p0;
            g_s2[t * 32768 + outIdx + 2048] = p1;
        }

        cp_wait0();
        __syncthreads();
    }
}

// ---------------------------------------------------------------------------
// conv2 (3x3,pad1,16->32) + psp+spike + 2x2 pool + psp+spike, fused. (R13 ver.)
// grid (hp=8, b=8, xq=4), 128 thr: xp = tid[0], kq = tid[1:2], co = tid>>3
// (0..15; channels co & co+16 packed). Tile: 16ci x 4r x 6c, CS=26
// (kq offsets -> banks {0,8,16,24}). Reduce-scatter over kq (masks 2,4).
// ---------------------------------------------------------------------------
#define C2_CS 26
__global__ void __launch_bounds__(128) conv2_fused_kernel(const float* __restrict__ W2) {
    __shared__ float sbuf[2][16 * C2_CS];  // [buf][ci*26 + r*6 + c]
    const int tid = threadIdx.x;
    const int xp  = tid & 1;
    const int kq  = (tid >> 1) & 3;
    const int co  = tid >> 3;             // 0..15 -> channels co, co+16
    const int hp  = blockIdx.x;           // 0..7
    const int b   = blockIdx.y;
    const int xq  = blockIdx.z;           // 0..3
    u64_t wp[36];
    #pragma unroll
    for (int k = 0; k < 36; ++k)
        wp[k] = pk2(W2[co * 144 + kq * 36 + k], W2[(co + 16) * 144 + kq * 36 + k]);
    for (int i = tid; i < 2 * 16 * C2_CS; i += 128) ((float*)sbuf)[i] = 0.f;

    bool sv[4] = {false, false, false, false}; int gg[4] = {0, 0, 0, 0};
    #pragma unroll
    for (int e = 0; e < 4; ++e) {
        int i = tid + e * 128;
        if (i >= 16 * C2_CS) break;
        int ci = i / C2_CS, rem = i - ci * C2_CS;
        if (rem < 24) {
            int r = rem / 6, c = rem - r * 6;
            int row = 2 * hp + r - 1, col = xq * 4 + c - 1;
            if (row >= 0 && row < 16 && col >= 0 && col < 16) {
                sv[e] = true; gg[e] = b * 4096 + ci * 256 + row * 16 + col;
            }
        }
    }
    __syncthreads();

    if (sv[0]) cp_async4(&sbuf[0][tid],       g_s2 + gg[0]);
    if (sv[1]) cp_async4(&sbuf[0][tid + 128], g_s2 + gg[1]);
    if (sv[2]) cp_async4(&sbuf[0][tid + 256], g_s2 + gg[2]);
    if (sv[3]) cp_async4(&sbuf[0][tid + 384], g_s2 + gg[3]);
    cp_commit(); cp_wait0();
    __syncthreads();

    Srm2 st = {0,0,0,0}, stP = {0,0,0,0};
    const int outIdx = ((b * 32 + co) * 8 + hp) * 8 + xq * 2 + xp;  // ch1 +1024

    #pragma unroll 1
    for (int t = 0; t < T_STEPS; ++t) {
        const int cur = t & 1;
        if (t + 1 < T_STEPS) {
            const float* fr = g_s2 + (t + 1) * 32768;
            if (sv[0]) cp_async4(&sbuf[cur ^ 1][tid],       fr + gg[0]);
            if (sv[1]) cp_async4(&sbuf[cur ^ 1][tid + 128], fr + gg[1]);
            if (sv[2]) cp_async4(&sbuf[cur ^ 1][tid + 256], fr + gg[2]);
            if (sv[3]) cp_async4(&sbuf[cur ^ 1][tid + 384], fr + gg[3]);
        }
        cp_commit();

        u64_t aA = 0ull, aB = 0ull, aC = 0ull, aD = 0ull;
        #pragma unroll
        for (int lci = 0; lci < 4; ++lci) {
            const float* sp_ = &sbuf[cur][(kq * 4 + lci) * C2_CS + 2 * xp];
            #pragma unroll
            for (int r = 0; r < 4; ++r) {
                float2 f0 = *(const float2*)(sp_ + r * 6);
                float2 f1 = *(const float2*)(sp_ + r * 6 + 2);
                u64_t vd[4];
                vd[0] = dup2(f0.x); vd[1] = dup2(f0.y);
                vd[2] = dup2(f1.x); vd[3] = dup2(f1.y);
                if (r < 3) {                       // y0: ky = r
                    #pragma unroll
                    for (int kx = 0; kx < 3; ++kx) {
                        aA = fma2(vd[kx],     wp[lci * 9 + r * 3 + kx], aA);
                        aB = fma2(vd[kx + 1], wp[lci * 9 + r * 3 + kx], aB);
                    }
                }
                if (r >= 1) {                      // y1: ky = r-1
                    #pragma unroll
                    for (int kx = 0; kx < 3; ++kx) {
                        aC = fma2(vd[kx],     wp[lci * 9 + (r - 1) * 3 + kx], aC);
                        aD = fma2(vd[kx + 1], wp[lci * 9 + (r - 1) * 3 + kx], aD);
                    }
                }
            }
        }
        // reduce-scatter over kq (lane bits 1,2): lane kq owns quad neuron kq.
        u64_t k0 = (kq & 1) ? aB : aA;
        u64_t k1 = (kq & 1) ? aD : aC;
        u64_t s0 = (kq & 1) ? aA : aB;
        u64_t s1 = (kq & 1) ? aC : aD;
        k0 = add2(k0, __shfl_xor_sync(0xffffffffu, s0, 2));
        k1 = add2(k1, __shfl_xor_sync(0xffffffffu, s1, 2));
        u64_t kk = (kq & 2) ? k1 : k0;
        u64_t ss = (kq & 2) ? k0 : k1;
        kk = add2(kk, __shfl_xor_sync(0xffffffffu, ss, 4));

        u64_t sp = srm2_step_pk(st, kk);
        u64_t r1 = add2(sp, __shfl_xor_sync(0xffffffffu, sp, 2));
        u64_t tot = add2(r1, __shfl_xor_sync(0xffffffffu, r1, 4));
        u64_t up = mul2(dup2(11.0f), tot);
        u64_t pp = srm2_step_pk(stP, up);
        if (kq == 0) {
            float p0, p1; upk2(pp, p0, p1);
            g_s4[t * 16384 + outIdx]        = p0;
            g_s4[t * 16384 + outIdx + 1024] = p1;
        }

        cp_wait0();
        __syncthreads();
    }
}

// ---------------------------------------------------------------------------
// fc1 GEMM: rows=(t,b) 2400, K=2048, N=512. 64x64 tile, 4x4 micro, kc=32,
// register double-buffered global loads, FFMA2 inner loop (bit-exact).
// ---------------------------------------------------------------------------
__global__ void __launch_bounds__(256) fc1_gemm_kernel(const float* __restrict__ Wf1) {
    __shared__ float As[32 * 68];
    __shared__ float Bs[32 * 68];
    const int tid = threadIdx.x;
    const int txn = tid & 15, tym = tid >> 4;
    const int m0 = blockIdx.x * 64, n0 = blockIdx.y * 64;
    u64_t acc2[4][2];
    #pragma unroll
    for (int i = 0; i < 4; ++i) { acc2[i][0] = 0ull; acc2[i][1] = 0ull; }

    float4 ra[2], rb[2];
    #pragma unroll
    for (int e = 0; e < 2; ++e) {
        int i = tid + e * 256, m = i >> 3, kq = i & 7, row = m0 + m;
        ra[e] = (row < 2400) ? *(const float4*)(g_s4 + row * 2048 + kq * 4)
                             : make_float4(0.f, 0.f, 0.f, 0.f);
        rb[e] = *(const float4*)(Wf1 + (n0 + m) * 2048 + kq * 4);
    }

    for (int kb = 0; kb < 2048; kb += 32) {
        #pragma unroll
        for (int e = 0; e < 2; ++e) {
            int i = tid + e * 256, m = i >> 3, kq = i & 7;
            As[(kq * 4 + 0) * 68 + m] = ra[e].x;
            As[(kq * 4 + 1) * 68 + m] = ra[e].y;
            As[(kq * 4 + 2) * 68 + m] = ra[e].z;
            As[(kq * 4 + 3) * 68 + m] = ra[e].w;
            Bs[(kq * 4 + 0) * 68 + m] = rb[e].x;
            Bs[(kq * 4 + 1) * 68 + m] = rb[e].y;
            Bs[(kq * 4 + 2) * 68 + m] = rb[e].z;
            Bs[(kq * 4 + 3) * 68 + m] = rb[e].w;
        }
        __syncthreads();
        if (kb + 32 < 2048) {
            #pragma unroll
            for (int e = 0; e < 2; ++e) {
                int i = tid + e * 256, m = i >> 3, kq = i & 7, row = m0 + m;
                ra[e] = (row < 2400) ? *(const float4*)(g_s4 + row * 2048 + kb + 32 + kq * 4)
                                     : make_float4(0.f, 0.f, 0.f, 0.f);
                rb[e] = *(const float4*)(Wf1 + (n0 + m) * 2048 + kb + 32 + kq * 4);
            }
        }
        #pragma unroll
        for (int k = 0; k < 32; ++k) {
            float4 aq = *(const float4*)&As[k * 68 + tym * 4];
            float4 bq = *(const float4*)&Bs[k * 68 + txn * 4];
            u64_t b01 = pk2(bq.x, bq.y);
            u64_t b23 = pk2(bq.z, bq.w);
            float av[4] = {aq.x, aq.y, aq.z, aq.w};
            #pragma unroll
            for (int i = 0; i < 4; ++i) {
                u64_t ai = dup2(av[i]);
                acc2[i][0] = fma2(ai, b01, acc2[i][0]);
                acc2[i][1] = fma2(ai, b23, acc2[i][1]);
            }
        }
        __syncthreads();
    }
    #pragma unroll
    for (int i = 0; i < 4; ++i) {
        int row = m0 + tym * 4 + i;
        if (row < 2400) {
            float4 v;
            upk2(acc2[i][0], v.x, v.y);
            upk2(acc2[i][1], v.z, v.w);
            *(float4*)(g_u5 + row * 512 + n0 + txn * 4) = v;
        }
    }
}

// ---------------------------------------------------------------------------
// fc2: float4 loads for both operands; single accumulator in ascending-c
// order (bit-identical to the scalar chain).
// ---------------------------------------------------------------------------
__global__ void fc2_kernel(const float* __restrict__ Wf2) {
    int idx = blockIdx.x * 256 + threadIdx.x;
    if (idx >= 2400 * 11) return;
    int row = idx / 11, o = idx % 11;
    const float4* a4 = (const float4*)(g_u5 + row * 512);
    const float4* w4 = (const float4*)(Wf2 + o * 512);
    float acc = 0.f;
    #pragma unroll 4
    for (int c = 0; c < 128; ++c) {
        float4 av = a4[c];
        float4 wv = w4[c];
        acc = fmaf(av.x, wv.x, acc);
        acc = fmaf(av.y, wv.y, acc);
        acc = fmaf(av.z, wv.z, acc);
        acc = fmaf(av.w, wv.w, acc);
    }
    g_u6[idx] = acc;
}

// final scan with g_u6 fully staged in shared memory (105.6 KB).
__global__ void final_scan_kernel(float* __restrict__ out) {
    extern __shared__ float su6[];        // 88*300 floats
    const int tid = threadIdx.x;
    for (int i = tid; i < 88 * T_STEPS; i += 128)
        su6[i] = g_u6[i];
    __syncthreads();
    int n = tid;
    if (n >= 88) return;
    Srm st = {0.f, 0.f, 0.f, 0.f};
    #pragma unroll 1
    for (int t = 0; t < T_STEPS; ++t) {
        float s = srm_step(st, su6[t * 88 + n]);
        out[n * 300 + t] = s;
    }
}

// ---------------------------------------------------------------------------
extern "C" void kernel_launch(void* const* d_in, const int* in_sizes, int n_in,
                              void* d_out, int out_size) {
    (void)in_sizes; (void)n_in; (void)out_size;
    const float* s_in = (const float*)d_in[0];
    const float* W1   = (const float*)d_in[1];
    const float* W2   = (const float*)d_in[2];
    const float* Wf1  = (const float*)d_in[3];
    const float* Wf2  = (const float*)d_in[4];
    float* out = (float*)d_out;

    pool0_transpose_kernel<<<dim3(3, 512), dim3(32, 8)>>>(s_in);
    scan_s0_kernel<<<64, 64>>>();
    conv1_fused_kernel<<<dim3(16, 8), 256>>>(W1);
    conv2_fused_kernel<<<dim3(8, 8, 4), 128>>>(W2);
    fc1_gemm_kernel<<<dim3(38, 8), 256>>>(Wf1);
    scan_u5_kernel<<<16, 64>>>();
    fc2_kernel<<<104, 256>>>(Wf2);
    cudaFuncSetAttribute(final_scan_kernel,
                         cudaFuncAttributeMaxDynamicSharedMemorySize,
                         88 * T_STEPS * (int)sizeof(float));
    final_scan_kernel<<<1, 128, 88 * T_STEPS * sizeof(float)>>>(out);
}